// round 14
// baseline (speedup 1.0000x reference)
#include <cuda_runtime.h>
#include <cuda_bf16.h>
#include <cstdint>
#include <math.h>

// Problem constants
#define T_SEQ   2048
#define C_EMB   1024
#define QKV_DIM 1536
#define N_HEAD  16
#define N_GRP   4
#define HEAD_D  64

// Scratch (allocation-free: __device__ globals)
__device__ float g_x  [T_SEQ * C_EMB];             // tf32-rounded x
__device__ float g_waT[QKV_DIM * C_EMB];           // tf32-rounded w_attn^T [N][K]
__device__ float g_wpT[C_EMB * C_EMB];             // tf32-rounded w_proj^T [N][K]
__device__ float g_qkv[T_SEQ * QKV_DIM];
__device__ float g_Q [N_HEAD * T_SEQ * HEAD_D];    // rounded, pre-scaled 1/8
__device__ float g_K [N_GRP * T_SEQ * HEAD_D];     // rounded, [grp][key][dim]
__device__ float g_V [N_GRP * T_SEQ * HEAD_D];     // rounded, [grp][key][dim]
__device__ float g_Vt[N_GRP * HEAD_D * T_SEQ];     // rounded, [grp][dim][key]
__device__ float g_Y [T_SEQ * C_EMB];              // rounded
__device__ float2 g_rope[T_SEQ * (HEAD_D / 2)];    // (cos,sin)

// ---------------------------------------------------------------------------
// helpers
// ---------------------------------------------------------------------------
__device__ __forceinline__ unsigned f2tf(float x) {
    unsigned r;
    asm("cvt.rna.tf32.f32 %0, %1;" : "=r"(r) : "f"(x));
    return r;
}
__device__ __forceinline__ float ftf(float x) {
    return __uint_as_float(f2tf(x));
}

__device__ __forceinline__ void mma_tf32(float c[4], const unsigned a[4],
                                         unsigned b0, unsigned b1) {
    asm volatile(
        "mma.sync.aligned.m16n8k8.row.col.f32.tf32.tf32.f32 "
        "{%0,%1,%2,%3}, {%4,%5,%6,%7}, {%8,%9}, {%0,%1,%2,%3};\n"
        : "+f"(c[0]), "+f"(c[1]), "+f"(c[2]), "+f"(c[3])
        : "r"(a[0]), "r"(a[1]), "r"(a[2]), "r"(a[3]), "r"(b0), "r"(b1));
}

__device__ __forceinline__ void ldsm4(unsigned r[4], uint32_t addr) {
    asm volatile(
        "ldmatrix.sync.aligned.m8n8.x4.shared.b16 {%0,%1,%2,%3}, [%4];\n"
        : "=r"(r[0]), "=r"(r[1]), "=r"(r[2]), "=r"(r[3]) : "r"(addr));
}

__device__ __forceinline__ void cp16(uint32_t dst_smem, const void* src) {
    asm volatile("cp.async.cg.shared.global [%0], [%1], 16;\n"
                 :: "r"(dst_smem), "l"(src));
}
__device__ __forceinline__ void cp_commit() {
    asm volatile("cp.async.commit_group;\n");
}
template <int N>
__device__ __forceinline__ void cp_wait() {
    asm volatile("cp.async.wait_group %0;\n" :: "n"(N));
}

// ---------------------------------------------------------------------------
// Pre-round to tf32 (elementwise)
// ---------------------------------------------------------------------------
__global__ void round_tf32(const float* __restrict__ in,
                           float* __restrict__ out, int n)
{
    int i = (blockIdx.x * blockDim.x + threadIdx.x) * 4;
    if (i >= n) return;
    float4 v = *(const float4*)(in + i);
    v.x = ftf(v.x); v.y = ftf(v.y); v.z = ftf(v.z); v.w = ftf(v.w);
    *(float4*)(out + i) = v;
}

// ---------------------------------------------------------------------------
// RoPE cos/sin table (identical float math to the inline original)
// ---------------------------------------------------------------------------
__global__ void build_rope()
{
    int idx = blockIdx.x * blockDim.x + threadIdx.x;
    if (idx >= T_SEQ * 32) return;
    int t = idx >> 5;
    int i = idx & 31;
    int d = 2 * i;
    float inv = powf(10000.0f, -(float)d / (float)HEAD_D);
    float ang = (float)t * inv;
    float s, c;
    sincosf(ang, &s, &c);
    g_rope[idx] = make_float2(c, s);
}

// ---------------------------------------------------------------------------
// Fused weight transpose+round: z=0 -> w_attn (1024x1536), z=1 -> w_proj
// (1024x1024). in[R][C] -> out[C][R], tf32-rounded. block (32,8).
// ---------------------------------------------------------------------------
__global__ void transpose_round2(const float* __restrict__ wa,
                                 const float* __restrict__ wp)
{
    __shared__ float tile[32][33];
    const int z = blockIdx.z;
    const int R = C_EMB;
    const int C = z ? C_EMB : QKV_DIM;
    if ((int)blockIdx.x * 32 >= C) return;
    const float* in  = z ? wp : wa;
    float* out       = z ? g_wpT : g_waT;

    int c0 = blockIdx.x * 32, r0 = blockIdx.y * 32;
    int tx = threadIdx.x, ty = threadIdx.y;
    #pragma unroll
    for (int i = 0; i < 32; i += 8)
        tile[ty + i][tx] = in[(size_t)(r0 + ty + i) * C + c0 + tx];
    __syncthreads();
    #pragma unroll
    for (int i = 0; i < 32; i += 8)
        out[(size_t)(c0 + ty + i) * R + r0 + tx] = ftf(tile[tx][ty + i]);
}

// ---------------------------------------------------------------------------
// V transpose (bit-move, already rounded): g_V [grp][key][dim] -> g_Vt
// [grp][dim][key]. Coalesced both sides.
// ---------------------------------------------------------------------------
__global__ void transpose_v()
{
    __shared__ float tile[32][33];
    int grp = blockIdx.z;
    int k0 = blockIdx.x * 32, d0 = blockIdx.y * 32;
    const float* src = g_V  + (size_t)grp * T_SEQ * HEAD_D;
    float*       dst = g_Vt + (size_t)grp * HEAD_D * T_SEQ;
    int tx = threadIdx.x, ty = threadIdx.y;
    #pragma unroll
    for (int i = 0; i < 32; i += 8)
        tile[ty + i][tx] = src[(size_t)(k0 + ty + i) * HEAD_D + d0 + tx];
    __syncthreads();
    #pragma unroll
    for (int i = 0; i < 32; i += 8)
        dst[(size_t)(d0 + ty + i) * T_SEQ + k0 + tx] = tile[tx][ty + i];
}

// ---------------------------------------------------------------------------
// tf32 GEMM, B transposed in gmem: C[M,N] = A[M,K] @ Bt[N,K]^T.
// Block tile 64x128, 8 warps (2Mx4N), warp tile 32x32, 256 threads,
// LDSM fragment loads. K-step 32 (R14: halves barrier/wait frequency),
// 3-stage cp.async pipeline. smem 83KB -> 2 CTAs/SM.
// ---------------------------------------------------------------------------
#define AS_STRIDE 36
#define BS_STRIDE 36
#define A_WORDS   (64 * AS_STRIDE)           // 2304
#define B_WORDS   (128 * BS_STRIDE)          // 4608
#define STAGE_WORDS (A_WORDS + B_WORDS)      // 6912
#define GEMM_SMEM (3 * STAGE_WORDS * 4)      // 82944 B

__device__ __forceinline__ void gemm_load_stage(
    uint32_t sbase, const float* A, const float* Bt,
    int m0, int n0, int k0, int K, int tid)
{
    uint32_t as = sbase;
    uint32_t bs = sbase + A_WORDS * 4;
    // A slab: 64 rows x 32 k : 512 float4, two per thread
    #pragma unroll
    for (int i = 0; i < 2; i++) {
        int f = tid + i * 256;
        int row = f >> 3, kc = (f & 7) * 4;
        cp16(as + (row * AS_STRIDE + kc) * 4,
             A + (size_t)(m0 + row) * K + k0 + kc);
    }
    // B slab: 128 n-rows x 32 k : 1024 float4, four per thread
    #pragma unroll
    for (int i = 0; i < 4; i++) {
        int f = tid + i * 256;
        int row = f >> 3, kc = (f & 7) * 4;
        cp16(bs + (row * BS_STRIDE + kc) * 4,
             Bt + (size_t)(n0 + row) * K + k0 + kc);
    }
}

__global__ __launch_bounds__(256) void gemm_tf32(
    const float* __restrict__ A, const float* __restrict__ Bt,
    float* __restrict__ C, int M, int N, int K)
{
    extern __shared__ float sm[];
    const uint32_t smem_u32 = (uint32_t)__cvta_generic_to_shared(sm);

    const int tid  = threadIdx.x;
    const int wid  = tid >> 5;
    const int lane = tid & 31;
    const int g    = lane >> 2;
    const int t    = lane & 3;
    const int wm   = wid & 1;
    const int wn   = wid >> 1;
    const int m0   = blockIdx.y * 64;
    const int n0   = blockIdx.x * 128;

    const int lrow = (lane & 7) + ((lane >> 3) & 1) * 8;
    const int lcol = (lane >> 4) * 4;

    int a_off[2], b_off[2];
    #pragma unroll
    for (int mt = 0; mt < 2; mt++)
        a_off[mt] = (wm * 32 + mt * 16 + lrow) * AS_STRIDE + lcol;
    #pragma unroll
    for (int p = 0; p < 2; p++)
        b_off[p] = A_WORDS + (wn * 32 + p * 16 + lrow) * BS_STRIDE + lcol;

    float acc[2][4][4];
    #pragma unroll
    for (int mt = 0; mt < 2; mt++)
        #pragma unroll
        for (int nt = 0; nt < 4; nt++)
            #pragma unroll
            for (int i = 0; i < 4; i++) acc[mt][nt][i] = 0.0f;

    gemm_load_stage(smem_u32, A, Bt, m0, n0, 0, K, tid);
    cp_commit();
    gemm_load_stage(smem_u32 + STAGE_WORDS * 4, A, Bt, m0, n0, 32, K, tid);
    cp_commit();

    int s = 0;
    for (int k0 = 0; k0 < K; k0 += 32) {
        cp_wait<1>();
        __syncthreads();
        if (k0 + 64 < K) {
            int s2 = s + 2; if (s2 >= 3) s2 -= 3;
            gemm_load_stage(smem_u32 + s2 * STAGE_WORDS * 4,
                            A, Bt, m0, n0, k0 + 64, K, tid);
        }
        cp_commit();

        const uint32_t sb = smem_u32 + s * STAGE_WORDS * 4;
        #pragma unroll
        for (int kk = 0; kk < 4; kk++) {
            const int k8 = kk * 8;
            unsigned a[2][4], bf[2][4];
            ldsm4(a[0],  sb + (a_off[0] + k8) * 4);
            ldsm4(a[1],  sb + (a_off[1] + k8) * 4);
            ldsm4(bf[0], sb + (b_off[0] + k8) * 4);
            ldsm4(bf[1], sb + (b_off[1] + k8) * 4);
            #pragma unroll
            for (int p = 0; p < 2; p++)
                #pragma unroll
                for (int sub = 0; sub < 2; sub++) {
                    unsigned b0 = bf[p][sub], b1 = bf[p][2 + sub];
                    #pragma unroll
                    for (int mt = 0; mt < 2; mt++)
                        mma_tf32(acc[mt][2 * p + sub], a[mt], b0, b1);
                }
        }
        s++; if (s >= 3) s -= 3;
    }

    #pragma unroll
    for (int mt = 0; mt < 2; mt++) {
        int r0 = m0 + wm * 32 + mt * 16 + g;
        #pragma unroll
        for (int nt = 0; nt < 4; nt++) {
            int c0 = n0 + wn * 32 + nt * 8 + 2 * t;
            *(float2*)&C[(size_t)r0 * N + c0] =
                make_float2(acc[mt][nt][0], acc[mt][nt][1]);
            *(float2*)&C[(size_t)(r0 + 8) * N + c0] =
                make_float2(acc[mt][nt][2], acc[mt][nt][3]);
        }
    }
}

// ---------------------------------------------------------------------------
// RoPE + split qkv[T,1536] -> Q (1/8-scaled), K, V — all [..][key][dim],
// fully coalesced writes. V transposed afterwards by transpose_v (bit-move).
// ---------------------------------------------------------------------------
__global__ void rope_split(const float* __restrict__ qkv)
{
    int idx = blockIdx.x * blockDim.x + threadIdx.x;
    const int total = T_SEQ * (QKV_DIM / 2);
    if (idx >= total) return;
    int t = idx / (QKV_DIM / 2);
    int p = idx - t * (QKV_DIM / 2);
    int col = p * 2;
    int gq = col / (6 * HEAD_D);
    int w = col - gq * (6 * HEAD_D);
    int slot = w / HEAD_D;
    int d = w - slot * HEAD_D;

    float x0 = qkv[(size_t)t * QKV_DIM + col];
    float x1 = qkv[(size_t)t * QKV_DIM + col + 1];

    if (slot < 5) {
        float2 cs = g_rope[t * 32 + (d >> 1)];
        float r0 = x0 * cs.x - x1 * cs.y;
        float r1 = x1 * cs.x + x0 * cs.y;
        x0 = r0; x1 = r1;
    }

    if (slot < 4) {
        int h = gq * 4 + slot;
        float* dst = g_Q + ((size_t)h * T_SEQ + t) * HEAD_D + d;
        dst[0] = ftf(x0 * 0.125f); dst[1] = ftf(x1 * 0.125f);
    } else if (slot == 4) {
        float* dst = g_K + ((size_t)gq * T_SEQ + t) * HEAD_D + d;
        dst[0] = ftf(x0); dst[1] = ftf(x1);
    } else {
        float* dst = g_V + ((size_t)gq * T_SEQ + t) * HEAD_D + d;
        dst[0] = ftf(x0); dst[1] = ftf(x1);
    }
}

// ---------------------------------------------------------------------------
// Flash-style causal attention — R10 configuration (best measured).
// 128 threads (4 warps), 64 queries/CTA, smem P, 2-buffer cp.async, LPT,
// LDSM fragment loads (K [key][dim], Vt [dim][key], P [q][key]).
// ---------------------------------------------------------------------------
#define KS_STRIDE 68
#define VS_STRIDE 68
#define PS_STRIDE 68
#define K_WORDS (64 * KS_STRIDE)
#define V_WORDS (64 * VS_STRIDE)
#define P_WORDS (64 * PS_STRIDE)
#define ATTN_SMEM ((2 * K_WORDS + 2 * V_WORDS + P_WORDS) * 4)   // 87040 B

__device__ __forceinline__ void attn_load_tile(
    uint32_t kbuf, uint32_t vbuf,
    const float* Kg, const float* VgT, int kbase, int tid)
{
    #pragma unroll
    for (int i = 0; i < 8; i++) {
        int f = tid + i * 128;
        int row = f >> 4;
        int c = (f & 15) * 4;
        cp16(kbuf + (row * KS_STRIDE + c) * 4,
             Kg + (size_t)(kbase + row) * HEAD_D + c);
        cp16(vbuf + (row * VS_STRIDE + c) * 4,
             VgT + (size_t)row * T_SEQ + kbase + c);
    }
}

__global__ __launch_bounds__(128) void attn_kernel()
{
    extern __shared__ float sm[];
    float* Ps = sm + 2 * K_WORDS + 2 * V_WORDS;
    const uint32_t su = (uint32_t)__cvta_generic_to_shared(sm);
    const uint32_t kbu[2] = { su, su + K_WORDS * 4 };
    const uint32_t vbu[2] = { su + 2 * K_WORDS * 4, su + (2 * K_WORDS + V_WORDS) * 4 };
    const uint32_t psu    = su + (2 * K_WORDS + 2 * V_WORDS) * 4;

    const int h    = blockIdx.x;
    const int qt   = gridDim.y - 1 - blockIdx.y;   // LPT
    const int tid  = threadIdx.x;
    const int w    = tid >> 5;
    const int lane = tid & 31;
    const int g    = lane >> 2;
    const int t    = lane & 3;
    const int grp  = h >> 2;
    const int qw0  = qt * 64 + w * 16;

    const int lrow = (lane & 7) + ((lane >> 3) & 1) * 8;
    const int lcol = (lane >> 4) * 4;

    const float* Kg  = g_K  + (size_t)grp * T_SEQ * HEAD_D;
    const float* VgT = g_Vt + (size_t)grp * HEAD_D * T_SEQ;

    unsigned qa[8][4];
    {
        const float* Qb = g_Q + ((size_t)h * T_SEQ + qw0) * HEAD_D;
        #pragma unroll
        for (int ks = 0; ks < 8; ks++) {
            qa[ks][0] = __float_as_uint(Qb[(size_t)(g    ) * HEAD_D + ks * 8 + t    ]);
            qa[ks][1] = __float_as_uint(Qb[(size_t)(g + 8) * HEAD_D + ks * 8 + t    ]);
            qa[ks][2] = __float_as_uint(Qb[(size_t)(g    ) * HEAD_D + ks * 8 + t + 4]);
            qa[ks][3] = __float_as_uint(Qb[(size_t)(g + 8) * HEAD_D + ks * 8 + t + 4]);
        }
    }

    float oc[8][4];
    #pragma unroll
    for (int nt = 0; nt < 8; nt++)
        #pragma unroll
        for (int i = 0; i < 4; i++) oc[nt][i] = 0.0f;
    float l0 = 0.0f, l1 = 0.0f;

    attn_load_tile(kbu[0], vbu[0], Kg, VgT, 0, tid);
    cp_commit();

    int buf = 0;
    for (int kt = 0; kt <= qt; kt++) {
        const int kbase = kt * 64;
        cp_wait<0>();
        __syncthreads();
        if (kt < qt) {
            attn_load_tile(kbu[buf ^ 1], vbu[buf ^ 1], Kg, VgT, kbase + 64, tid);
        }
        cp_commit();

        const uint32_t kb = kbu[buf];
        const uint32_t vb = vbu[buf];

        // S = Q @ K^T
        float sc[8][4];
        #pragma unroll
        for (int nt = 0; nt < 8; nt++)
            #pragma unroll
            for (int i = 0; i < 4; i++) sc[nt][i] = 0.0f;

        #pragma unroll
        for (int ks = 0; ks < 8; ks++) {
            #pragma unroll
            for (int p = 0; p < 4; p++) {
                unsigned bf[4];
                ldsm4(bf, kb + ((p * 16 + lrow) * KS_STRIDE + ks * 8 + lcol) * 4);
                mma_tf32(sc[2 * p    ], qa[ks], bf[0], bf[2]);
                mma_tf32(sc[2 * p + 1], qa[ks], bf[1], bf[3]);
            }
        }

        // exp (+causal mask on diagonal), accumulate l, store P (tf32)
        const bool diag = (kt == qt);
        #pragma unroll
        for (int nt = 0; nt < 8; nt++) {
            int k0 = kbase + nt * 8 + 2 * t;
            float p0 = __expf(sc[nt][0]);
            float p1 = __expf(sc[nt][1]);
            float p2 = __expf(sc[nt][2]);
            float p3 = __expf(sc[nt][3]);
            if (diag) {
                int q0 = qw0 + g, q1 = qw0 + g + 8;
                if (k0     > q0) p0 = 0.0f;
                if (k0 + 1 > q0) p1 = 0.0f;
                if (k0     > q1) p2 = 0.0f;
                if (k0 + 1 > q1) p3 = 0.0f;
            }
            l0 += p0 + p1;
            l1 += p2 + p3;
            int c = nt * 8 + 2 * t;
            Ps[(w * 16 + g    ) * PS_STRIDE + c    ] = ftf(p0);
            Ps[(w * 16 + g    ) * PS_STRIDE + c + 1] = ftf(p1);
            Ps[(w * 16 + g + 8) * PS_STRIDE + c    ] = ftf(p2);
            Ps[(w * 16 + g + 8) * PS_STRIDE + c + 1] = ftf(p3);
        }
        __syncwarp();   // Ps slab is warp-private

        // O += P @ V
        #pragma unroll
        for (int ks = 0; ks < 8; ks++) {
            unsigned pa[4];
            ldsm4(pa, psu + ((w * 16 + lrow) * PS_STRIDE + ks * 8 + lcol) * 4);
            #pragma unroll
            for (int p = 0; p < 4; p++) {
                unsigned bf[4];
                ldsm4(bf, vb + ((p * 16 + lrow) * VS_STRIDE + ks * 8 + lcol) * 4);
                mma_tf32(oc[2 * p    ], pa, bf[0], bf[2]);
                mma_tf32(oc[2 * p + 1], pa, bf[1], bf[3]);
            }
        }
        buf ^= 1;
    }

    l0 += __shfl_xor_sync(0xffffffff, l0, 1);
    l0 += __shfl_xor_sync(0xffffffff, l0, 2);
    l1 += __shfl_xor_sync(0xffffffff, l1, 1);
    l1 += __shfl_xor_sync(0xffffffff, l1, 2);
    float inv0 = 1.0f / l0;
    float inv1 = 1.0f / l1;

    float* Y0 = g_Y + (size_t)(qw0 + g    ) * C_EMB + h * HEAD_D;
    float* Y1 = g_Y + (size_t)(qw0 + g + 8) * C_EMB + h * HEAD_D;
    #pragma unroll
    for (int nt = 0; nt < 8; nt++) {
        int c = nt * 8 + 2 * t;
        *(float2*)(Y0 + c) = make_float2(ftf(oc[nt][0] * inv0), ftf(oc[nt][1] * inv0));
        *(float2*)(Y1 + c) = make_float2(ftf(oc[nt][2] * inv1), ftf(oc[nt][3] * inv1));
    }
}

// ---------------------------------------------------------------------------
extern "C" void kernel_launch(void* const* d_in, const int* in_sizes, int n_in,
                              void* d_out, int out_size)
{
    const float* x      = (const float*)d_in[0];   // [1,2048,1024]
    const float* w_attn = (const float*)d_in[1];   // [1024,1536]
    const float* w_proj = (const float*)d_in[2];   // [1024,1024]
    float* out = (float*)d_out;                    // [1,2048,1024]

    float *xr, *qkv, *Y, *waT, *wpT;
    cudaGetSymbolAddress((void**)&xr,  g_x);
    cudaGetSymbolAddress((void**)&waT, g_waT);
    cudaGetSymbolAddress((void**)&wpT, g_wpT);
    cudaGetSymbolAddress((void**)&qkv, g_qkv);
    cudaGetSymbolAddress((void**)&Y,   g_Y);

    cudaFuncSetAttribute(gemm_tf32,
                         cudaFuncAttributeMaxDynamicSharedMemorySize, GEMM_SMEM);
    cudaFuncSetAttribute(attn_kernel,
                         cudaFuncAttributeMaxDynamicSharedMemorySize, ATTN_SMEM);

    // launch 0: round x
    {
        int n1 = T_SEQ * C_EMB;
        round_tf32<<<(n1 / 4 + 255) / 256, 256>>>(x, xr, n1);
    }
    // launch 1: rope table
    build_rope<<<(T_SEQ * 32 + 255) / 256, 256>>>();
    // launch 2: both weight transposes (fused)
    transpose_round2<<<dim3(QKV_DIM / 32, C_EMB / 32, 2), dim3(32, 8)>>>(
        w_attn, w_proj);
    // launch 3 (PROFILED): QKV = x @ w_attn
    {
        dim3 grid(QKV_DIM / 128, T_SEQ / 64);
        gemm_tf32<<<grid, 256, GEMM_SMEM>>>(xr, waT, qkv, T_SEQ, QKV_DIM, C_EMB);
    }
    // launch 4: RoPE + split
    {
        int total = T_SEQ * (QKV_DIM / 2);
        rope_split<<<(total + 255) / 256, 256>>>(qkv);
    }
    // launch 5: V transpose
    transpose_v<<<dim3(T_SEQ / 32, HEAD_D / 32, N_GRP), dim3(32, 8)>>>();
    // launch 6: attention
    {
        dim3 grid(N_HEAD, T_SEQ / 64);
        attn_kernel<<<grid, 128, ATTN_SMEM>>>();
    }
    // launch 7: out = Y @ w_proj
    {
        dim3 grid(C_EMB / 128, T_SEQ / 64);
        gemm_tf32<<<grid, 256, GEMM_SMEM>>>(Y, wpT, out, T_SEQ, C_EMB, C_EMB);
    }
}

// round 15
// speedup vs baseline: 1.0242x; 1.0242x over previous
#include <cuda_runtime.h>
#include <cuda_bf16.h>
#include <cstdint>
#include <math.h>

// Problem constants
#define T_SEQ   2048
#define C_EMB   1024
#define QKV_DIM 1536
#define N_HEAD  16
#define N_GRP   4
#define HEAD_D  64

// Scratch (allocation-free: __device__ globals)
__device__ float g_x  [T_SEQ * C_EMB];             // tf32-rounded x
__device__ float g_waT[QKV_DIM * C_EMB];           // tf32-rounded w_attn^T [N][K]
__device__ float g_wpT[C_EMB * C_EMB];             // tf32-rounded w_proj^T [N][K]
__device__ float g_qkv[T_SEQ * QKV_DIM];
__device__ float g_Q [N_HEAD * T_SEQ * HEAD_D];    // rounded, pre-scaled 1/8
__device__ float g_K [N_GRP * T_SEQ * HEAD_D];     // rounded, [grp][key][dim]
__device__ float g_V [N_GRP * T_SEQ * HEAD_D];     // rounded, [grp][key][dim]
__device__ float g_Vt[N_GRP * HEAD_D * T_SEQ];     // rounded, [grp][dim][key]
__device__ float g_Y [T_SEQ * C_EMB];              // rounded
__device__ float2 g_rope[T_SEQ * (HEAD_D / 2)];    // (cos,sin)

// ---------------------------------------------------------------------------
// helpers
// ---------------------------------------------------------------------------
__device__ __forceinline__ unsigned f2tf(float x) {
    unsigned r;
    asm("cvt.rna.tf32.f32 %0, %1;" : "=r"(r) : "f"(x));
    return r;
}
__device__ __forceinline__ float ftf(float x) {
    return __uint_as_float(f2tf(x));
}

__device__ __forceinline__ void mma_tf32(float c[4], const unsigned a[4],
                                         unsigned b0, unsigned b1) {
    asm volatile(
        "mma.sync.aligned.m16n8k8.row.col.f32.tf32.tf32.f32 "
        "{%0,%1,%2,%3}, {%4,%5,%6,%7}, {%8,%9}, {%0,%1,%2,%3};\n"
        : "+f"(c[0]), "+f"(c[1]), "+f"(c[2]), "+f"(c[3])
        : "r"(a[0]), "r"(a[1]), "r"(a[2]), "r"(a[3]), "r"(b0), "r"(b1));
}

__device__ __forceinline__ void ldsm4(unsigned r[4], uint32_t addr) {
    asm volatile(
        "ldmatrix.sync.aligned.m8n8.x4.shared.b16 {%0,%1,%2,%3}, [%4];\n"
        : "=r"(r[0]), "=r"(r[1]), "=r"(r[2]), "=r"(r[3]) : "r"(addr));
}

__device__ __forceinline__ void cp16(uint32_t dst_smem, const void* src) {
    asm volatile("cp.async.cg.shared.global [%0], [%1], 16;\n"
                 :: "r"(dst_smem), "l"(src));
}
__device__ __forceinline__ void cp_commit() {
    asm volatile("cp.async.commit_group;\n");
}
template <int N>
__device__ __forceinline__ void cp_wait() {
    asm volatile("cp.async.wait_group %0;\n" :: "n"(N));
}

// ---------------------------------------------------------------------------
// Pre-round to tf32 (elementwise)
// ---------------------------------------------------------------------------
__global__ void round_tf32(const float* __restrict__ in,
                           float* __restrict__ out, int n)
{
    int i = (blockIdx.x * blockDim.x + threadIdx.x) * 4;
    if (i >= n) return;
    float4 v = *(const float4*)(in + i);
    v.x = ftf(v.x); v.y = ftf(v.y); v.z = ftf(v.z); v.w = ftf(v.w);
    *(float4*)(out + i) = v;
}

// ---------------------------------------------------------------------------
// RoPE cos/sin table (identical float math to the inline original)
// ---------------------------------------------------------------------------
__global__ void build_rope()
{
    int idx = blockIdx.x * blockDim.x + threadIdx.x;
    if (idx >= T_SEQ * 32) return;
    int t = idx >> 5;
    int i = idx & 31;
    int d = 2 * i;
    float inv = powf(10000.0f, -(float)d / (float)HEAD_D);
    float ang = (float)t * inv;
    float s, c;
    sincosf(ang, &s, &c);
    g_rope[idx] = make_float2(c, s);
}

// ---------------------------------------------------------------------------
// Fused weight transpose+round: z=0 -> w_attn (1024x1536), z=1 -> w_proj
// (1024x1024). in[R][C] -> out[C][R], tf32-rounded. block (32,8).
// ---------------------------------------------------------------------------
__global__ void transpose_round2(const float* __restrict__ wa,
                                 const float* __restrict__ wp)
{
    __shared__ float tile[32][33];
    const int z = blockIdx.z;
    const int R = C_EMB;
    const int C = z ? C_EMB : QKV_DIM;
    if ((int)blockIdx.x * 32 >= C) return;
    const float* in  = z ? wp : wa;
    float* out       = z ? g_wpT : g_waT;

    int c0 = blockIdx.x * 32, r0 = blockIdx.y * 32;
    int tx = threadIdx.x, ty = threadIdx.y;
    #pragma unroll
    for (int i = 0; i < 32; i += 8)
        tile[ty + i][tx] = in[(size_t)(r0 + ty + i) * C + c0 + tx];
    __syncthreads();
    #pragma unroll
    for (int i = 0; i < 32; i += 8)
        out[(size_t)(c0 + ty + i) * R + r0 + tx] = ftf(tile[tx][ty + i]);
}

// ---------------------------------------------------------------------------
// V transpose (bit-move, already rounded): g_V [grp][key][dim] -> g_Vt
// [grp][dim][key]. Coalesced both sides.
// ---------------------------------------------------------------------------
__global__ void transpose_v()
{
    __shared__ float tile[32][33];
    int grp = blockIdx.z;
    int k0 = blockIdx.x * 32, d0 = blockIdx.y * 32;
    const float* src = g_V  + (size_t)grp * T_SEQ * HEAD_D;
    float*       dst = g_Vt + (size_t)grp * HEAD_D * T_SEQ;
    int tx = threadIdx.x, ty = threadIdx.y;
    #pragma unroll
    for (int i = 0; i < 32; i += 8)
        tile[ty + i][tx] = src[(size_t)(k0 + ty + i) * HEAD_D + d0 + tx];
    __syncthreads();
    #pragma unroll
    for (int i = 0; i < 32; i += 8)
        dst[(size_t)(d0 + ty + i) * T_SEQ + k0 + tx] = tile[tx][ty + i];
}

// ---------------------------------------------------------------------------
// tf32 GEMM, B transposed in gmem: C[M,N] = A[M,K] @ Bt[N,K]^T.
// Block tile 64x128, 8 warps (2Mx4N), warp tile 32x32, 256 threads,
// LDSM fragment loads. K-step 32, 2-STAGE pipeline (attention-style:
// one cp_wait<0> + one __syncthreads per iteration; load(k+1) overlaps
// compute(k)). smem 55KB -> occupancy back to grid limit (~2.6 CTAs/SM),
// 32-mma bursts per warp between barriers.
// ---------------------------------------------------------------------------
#define AS_STRIDE 36
#define BS_STRIDE 36
#define A_WORDS   (64 * AS_STRIDE)           // 2304
#define B_WORDS   (128 * BS_STRIDE)          // 4608
#define STAGE_WORDS (A_WORDS + B_WORDS)      // 6912
#define GEMM_SMEM (2 * STAGE_WORDS * 4)      // 55296 B

__device__ __forceinline__ void gemm_load_stage(
    uint32_t sbase, const float* A, const float* Bt,
    int m0, int n0, int k0, int K, int tid)
{
    uint32_t as = sbase;
    uint32_t bs = sbase + A_WORDS * 4;
    // A slab: 64 rows x 32 k : 512 float4, two per thread
    #pragma unroll
    for (int i = 0; i < 2; i++) {
        int f = tid + i * 256;
        int row = f >> 3, kc = (f & 7) * 4;
        cp16(as + (row * AS_STRIDE + kc) * 4,
             A + (size_t)(m0 + row) * K + k0 + kc);
    }
    // B slab: 128 n-rows x 32 k : 1024 float4, four per thread
    #pragma unroll
    for (int i = 0; i < 4; i++) {
        int f = tid + i * 256;
        int row = f >> 3, kc = (f & 7) * 4;
        cp16(bs + (row * BS_STRIDE + kc) * 4,
             Bt + (size_t)(n0 + row) * K + k0 + kc);
    }
}

__global__ __launch_bounds__(256) void gemm_tf32(
    const float* __restrict__ A, const float* __restrict__ Bt,
    float* __restrict__ C, int M, int N, int K)
{
    extern __shared__ float sm[];
    const uint32_t smem_u32 = (uint32_t)__cvta_generic_to_shared(sm);

    const int tid  = threadIdx.x;
    const int wid  = tid >> 5;
    const int lane = tid & 31;
    const int g    = lane >> 2;
    const int t    = lane & 3;
    const int wm   = wid & 1;
    const int wn   = wid >> 1;
    const int m0   = blockIdx.y * 64;
    const int n0   = blockIdx.x * 128;

    const int lrow = (lane & 7) + ((lane >> 3) & 1) * 8;
    const int lcol = (lane >> 4) * 4;

    int a_off[2], b_off[2];
    #pragma unroll
    for (int mt = 0; mt < 2; mt++)
        a_off[mt] = (wm * 32 + mt * 16 + lrow) * AS_STRIDE + lcol;
    #pragma unroll
    for (int p = 0; p < 2; p++)
        b_off[p] = A_WORDS + (wn * 32 + p * 16 + lrow) * BS_STRIDE + lcol;

    float acc[2][4][4];
    #pragma unroll
    for (int mt = 0; mt < 2; mt++)
        #pragma unroll
        for (int nt = 0; nt < 4; nt++)
            #pragma unroll
            for (int i = 0; i < 4; i++) acc[mt][nt][i] = 0.0f;

    gemm_load_stage(smem_u32, A, Bt, m0, n0, 0, K, tid);
    cp_commit();

    int s = 0;
    for (int k0 = 0; k0 < K; k0 += 32) {
        cp_wait<0>();
        __syncthreads();
        // buffer s ready; buffer s^1 fully consumed (barrier above covers
        // the previous iteration's compute) -> safe to refill
        if (k0 + 32 < K) {
            gemm_load_stage(smem_u32 + (s ^ 1) * STAGE_WORDS * 4,
                            A, Bt, m0, n0, k0 + 32, K, tid);
        }
        cp_commit();

        const uint32_t sb = smem_u32 + s * STAGE_WORDS * 4;
        #pragma unroll
        for (int kk = 0; kk < 4; kk++) {
            const int k8 = kk * 8;
            unsigned a[2][4], bf[2][4];
            ldsm4(a[0],  sb + (a_off[0] + k8) * 4);
            ldsm4(a[1],  sb + (a_off[1] + k8) * 4);
            ldsm4(bf[0], sb + (b_off[0] + k8) * 4);
            ldsm4(bf[1], sb + (b_off[1] + k8) * 4);
            #pragma unroll
            for (int p = 0; p < 2; p++)
                #pragma unroll
                for (int sub = 0; sub < 2; sub++) {
                    unsigned b0 = bf[p][sub], b1 = bf[p][2 + sub];
                    #pragma unroll
                    for (int mt = 0; mt < 2; mt++)
                        mma_tf32(acc[mt][2 * p + sub], a[mt], b0, b1);
                }
        }
        s ^= 1;
    }

    #pragma unroll
    for (int mt = 0; mt < 2; mt++) {
        int r0 = m0 + wm * 32 + mt * 16 + g;
        #pragma unroll
        for (int nt = 0; nt < 4; nt++) {
            int c0 = n0 + wn * 32 + nt * 8 + 2 * t;
            *(float2*)&C[(size_t)r0 * N + c0] =
                make_float2(acc[mt][nt][0], acc[mt][nt][1]);
            *(float2*)&C[(size_t)(r0 + 8) * N + c0] =
                make_float2(acc[mt][nt][2], acc[mt][nt][3]);
        }
    }
}

// ---------------------------------------------------------------------------
// RoPE + split qkv[T,1536] -> Q (1/8-scaled), K, V — all [..][key][dim],
// fully coalesced writes. V transposed afterwards by transpose_v (bit-move).
// ---------------------------------------------------------------------------
__global__ void rope_split(const float* __restrict__ qkv)
{
    int idx = blockIdx.x * blockDim.x + threadIdx.x;
    const int total = T_SEQ * (QKV_DIM / 2);
    if (idx >= total) return;
    int t = idx / (QKV_DIM / 2);
    int p = idx - t * (QKV_DIM / 2);
    int col = p * 2;
    int gq = col / (6 * HEAD_D);
    int w = col - gq * (6 * HEAD_D);
    int slot = w / HEAD_D;
    int d = w - slot * HEAD_D;

    float x0 = qkv[(size_t)t * QKV_DIM + col];
    float x1 = qkv[(size_t)t * QKV_DIM + col + 1];

    if (slot < 5) {
        float2 cs = g_rope[t * 32 + (d >> 1)];
        float r0 = x0 * cs.x - x1 * cs.y;
        float r1 = x1 * cs.x + x0 * cs.y;
        x0 = r0; x1 = r1;
    }

    if (slot < 4) {
        int h = gq * 4 + slot;
        float* dst = g_Q + ((size_t)h * T_SEQ + t) * HEAD_D + d;
        dst[0] = ftf(x0 * 0.125f); dst[1] = ftf(x1 * 0.125f);
    } else if (slot == 4) {
        float* dst = g_K + ((size_t)gq * T_SEQ + t) * HEAD_D + d;
        dst[0] = ftf(x0); dst[1] = ftf(x1);
    } else {
        float* dst = g_V + ((size_t)gq * T_SEQ + t) * HEAD_D + d;
        dst[0] = ftf(x0); dst[1] = ftf(x1);
    }
}

// ---------------------------------------------------------------------------
// Flash-style causal attention — R10 configuration (best measured).
// 128 threads (4 warps), 64 queries/CTA, smem P, 2-buffer cp.async, LPT,
// LDSM fragment loads (K [key][dim], Vt [dim][key], P [q][key]).
// ---------------------------------------------------------------------------
#define KS_STRIDE 68
#define VS_STRIDE 68
#define PS_STRIDE 68
#define K_WORDS (64 * KS_STRIDE)
#define V_WORDS (64 * VS_STRIDE)
#define P_WORDS (64 * PS_STRIDE)
#define ATTN_SMEM ((2 * K_WORDS + 2 * V_WORDS + P_WORDS) * 4)   // 87040 B

__device__ __forceinline__ void attn_load_tile(
    uint32_t kbuf, uint32_t vbuf,
    const float* Kg, const float* VgT, int kbase, int tid)
{
    #pragma unroll
    for (int i = 0; i < 8; i++) {
        int f = tid + i * 128;
        int row = f >> 4;
        int c = (f & 15) * 4;
        cp16(kbuf + (row * KS_STRIDE + c) * 4,
             Kg + (size_t)(kbase + row) * HEAD_D + c);
        cp16(vbuf + (row * VS_STRIDE + c) * 4,
             VgT + (size_t)row * T_SEQ + kbase + c);
    }
}

__global__ __launch_bounds__(128) void attn_kernel()
{
    extern __shared__ float sm[];
    float* Ps = sm + 2 * K_WORDS + 2 * V_WORDS;
    const uint32_t su = (uint32_t)__cvta_generic_to_shared(sm);
    const uint32_t kbu[2] = { su, su + K_WORDS * 4 };
    const uint32_t vbu[2] = { su + 2 * K_WORDS * 4, su + (2 * K_WORDS + V_WORDS) * 4 };
    const uint32_t psu    = su + (2 * K_WORDS + 2 * V_WORDS) * 4;

    const int h    = blockIdx.x;
    const int qt   = gridDim.y - 1 - blockIdx.y;   // LPT
    const int tid  = threadIdx.x;
    const int w    = tid >> 5;
    const int lane = tid & 31;
    const int g    = lane >> 2;
    const int t    = lane & 3;
    const int grp  = h >> 2;
    const int qw0  = qt * 64 + w * 16;

    const int lrow = (lane & 7) + ((lane >> 3) & 1) * 8;
    const int lcol = (lane >> 4) * 4;

    const float* Kg  = g_K  + (size_t)grp * T_SEQ * HEAD_D;
    const float* VgT = g_Vt + (size_t)grp * HEAD_D * T_SEQ;

    unsigned qa[8][4];
    {
        const float* Qb = g_Q + ((size_t)h * T_SEQ + qw0) * HEAD_D;
        #pragma unroll
        for (int ks = 0; ks < 8; ks++) {
            qa[ks][0] = __float_as_uint(Qb[(size_t)(g    ) * HEAD_D + ks * 8 + t    ]);
            qa[ks][1] = __float_as_uint(Qb[(size_t)(g + 8) * HEAD_D + ks * 8 + t    ]);
            qa[ks][2] = __float_as_uint(Qb[(size_t)(g    ) * HEAD_D + ks * 8 + t + 4]);
            qa[ks][3] = __float_as_uint(Qb[(size_t)(g + 8) * HEAD_D + ks * 8 + t + 4]);
        }
    }

    float oc[8][4];
    #pragma unroll
    for (int nt = 0; nt < 8; nt++)
        #pragma unroll
        for (int i = 0; i < 4; i++) oc[nt][i] = 0.0f;
    float l0 = 0.0f, l1 = 0.0f;

    attn_load_tile(kbu[0], vbu[0], Kg, VgT, 0, tid);
    cp_commit();

    int buf = 0;
    for (int kt = 0; kt <= qt; kt++) {
        const int kbase = kt * 64;
        cp_wait<0>();
        __syncthreads();
        if (kt < qt) {
            attn_load_tile(kbu[buf ^ 1], vbu[buf ^ 1], Kg, VgT, kbase + 64, tid);
        }
        cp_commit();

        const uint32_t kb = kbu[buf];
        const uint32_t vb = vbu[buf];

        // S = Q @ K^T
        float sc[8][4];
        #pragma unroll
        for (int nt = 0; nt < 8; nt++)
            #pragma unroll
            for (int i = 0; i < 4; i++) sc[nt][i] = 0.0f;

        #pragma unroll
        for (int ks = 0; ks < 8; ks++) {
            #pragma unroll
            for (int p = 0; p < 4; p++) {
                unsigned bf[4];
                ldsm4(bf, kb + ((p * 16 + lrow) * KS_STRIDE + ks * 8 + lcol) * 4);
                mma_tf32(sc[2 * p    ], qa[ks], bf[0], bf[2]);
                mma_tf32(sc[2 * p + 1], qa[ks], bf[1], bf[3]);
            }
        }

        // exp (+causal mask on diagonal), accumulate l, store P (tf32)
        const bool diag = (kt == qt);
        #pragma unroll
        for (int nt = 0; nt < 8; nt++) {
            int k0 = kbase + nt * 8 + 2 * t;
            float p0 = __expf(sc[nt][0]);
            float p1 = __expf(sc[nt][1]);
            float p2 = __expf(sc[nt][2]);
            float p3 = __expf(sc[nt][3]);
            if (diag) {
                int q0 = qw0 + g, q1 = qw0 + g + 8;
                if (k0     > q0) p0 = 0.0f;
                if (k0 + 1 > q0) p1 = 0.0f;
                if (k0     > q1) p2 = 0.0f;
                if (k0 + 1 > q1) p3 = 0.0f;
            }
            l0 += p0 + p1;
            l1 += p2 + p3;
            int c = nt * 8 + 2 * t;
            Ps[(w * 16 + g    ) * PS_STRIDE + c    ] = ftf(p0);
            Ps[(w * 16 + g    ) * PS_STRIDE + c + 1] = ftf(p1);
            Ps[(w * 16 + g + 8) * PS_STRIDE + c    ] = ftf(p2);
            Ps[(w * 16 + g + 8) * PS_STRIDE + c + 1] = ftf(p3);
        }
        __syncwarp();   // Ps slab is warp-private

        // O += P @ V
        #pragma unroll
        for (int ks = 0; ks < 8; ks++) {
            unsigned pa[4];
            ldsm4(pa, psu + ((w * 16 + lrow) * PS_STRIDE + ks * 8 + lcol) * 4);
            #pragma unroll
            for (int p = 0; p < 4; p++) {
                unsigned bf[4];
                ldsm4(bf, vb + ((p * 16 + lrow) * VS_STRIDE + ks * 8 + lcol) * 4);
                mma_tf32(oc[2 * p    ], pa, bf[0], bf[2]);
                mma_tf32(oc[2 * p + 1], pa, bf[1], bf[3]);
            }
        }
        buf ^= 1;
    }

    l0 += __shfl_xor_sync(0xffffffff, l0, 1);
    l0 += __shfl_xor_sync(0xffffffff, l0, 2);
    l1 += __shfl_xor_sync(0xffffffff, l1, 1);
    l1 += __shfl_xor_sync(0xffffffff, l1, 2);
    float inv0 = 1.0f / l0;
    float inv1 = 1.0f / l1;

    float* Y0 = g_Y + (size_t)(qw0 + g    ) * C_EMB + h * HEAD_D;
    float* Y1 = g_Y + (size_t)(qw0 + g + 8) * C_EMB + h * HEAD_D;
    #pragma unroll
    for (int nt = 0; nt < 8; nt++) {
        int c = nt * 8 + 2 * t;
        *(float2*)(Y0 + c) = make_float2(ftf(oc[nt][0] * inv0), ftf(oc[nt][1] * inv0));
        *(float2*)(Y1 + c) = make_float2(ftf(oc[nt][2] * inv1), ftf(oc[nt][3] * inv1));
    }
}

// ---------------------------------------------------------------------------
extern "C" void kernel_launch(void* const* d_in, const int* in_sizes, int n_in,
                              void* d_out, int out_size)
{
    const float* x      = (const float*)d_in[0];   // [1,2048,1024]
    const float* w_attn = (const float*)d_in[1];   // [1024,1536]
    const float* w_proj = (const float*)d_in[2];   // [1024,1024]
    float* out = (float*)d_out;                    // [1,2048,1024]

    float *xr, *qkv, *Y, *waT, *wpT;
    cudaGetSymbolAddress((void**)&xr,  g_x);
    cudaGetSymbolAddress((void**)&waT, g_waT);
    cudaGetSymbolAddress((void**)&wpT, g_wpT);
    cudaGetSymbolAddress((void**)&qkv, g_qkv);
    cudaGetSymbolAddress((void**)&Y,   g_Y);

    cudaFuncSetAttribute(gemm_tf32,
                         cudaFuncAttributeMaxDynamicSharedMemorySize, GEMM_SMEM);
    cudaFuncSetAttribute(attn_kernel,
                         cudaFuncAttributeMaxDynamicSharedMemorySize, ATTN_SMEM);

    // launch 0: round x
    {
        int n1 = T_SEQ * C_EMB;
        round_tf32<<<(n1 / 4 + 255) / 256, 256>>>(x, xr, n1);
    }
    // launch 1: rope table
    build_rope<<<(T_SEQ * 32 + 255) / 256, 256>>>();
    // launch 2: both weight transposes (fused)
    transpose_round2<<<dim3(QKV_DIM / 32, C_EMB / 32, 2), dim3(32, 8)>>>(
        w_attn, w_proj);
    // launch 3 (PROFILED): QKV = x @ w_attn
    {
        dim3 grid(QKV_DIM / 128, T_SEQ / 64);
        gemm_tf32<<<grid, 256, GEMM_SMEM>>>(xr, waT, qkv, T_SEQ, QKV_DIM, C_EMB);
    }
    // launch 4: RoPE + split
    {
        int total = T_SEQ * (QKV_DIM / 2);
        rope_split<<<(total + 255) / 256, 256>>>(qkv);
    }
    // launch 5: V transpose
    transpose_v<<<dim3(T_SEQ / 32, HEAD_D / 32, N_GRP), dim3(32, 8)>>>();
    // launch 6: attention
    {
        dim3 grid(N_HEAD, T_SEQ / 64);
        attn_kernel<<<grid, 128, ATTN_SMEM>>>();
    }
    // launch 7: out = Y @ w_proj
    {
        dim3 grid(C_EMB / 128, T_SEQ / 64);
        gemm_tf32<<<grid, 256, GEMM_SMEM>>>(Y, wpT, out, T_SEQ, C_EMB, C_EMB);
    }
}

// round 16
// speedup vs baseline: 1.0464x; 1.0217x over previous
#include <cuda_runtime.h>
#include <cuda_bf16.h>
#include <cstdint>
#include <math.h>

// Problem constants
#define T_SEQ   2048
#define C_EMB   1024
#define QKV_DIM 1536
#define N_HEAD  16
#define N_GRP   4
#define HEAD_D  64

// Scratch (allocation-free: __device__ globals)
__device__ float g_x  [T_SEQ * C_EMB];             // tf32-rounded x
__device__ float g_waT[QKV_DIM * C_EMB];           // tf32-rounded w_attn^T [N][K]
__device__ float g_wpT[C_EMB * C_EMB];             // tf32-rounded w_proj^T [N][K]
__device__ float g_qkv[T_SEQ * QKV_DIM];
__device__ float g_Q [N_HEAD * T_SEQ * HEAD_D];    // rounded, pre-scaled 1/8
__device__ float g_K [N_GRP * T_SEQ * HEAD_D];     // rounded, [grp][key][dim]
__device__ float g_Vt[N_GRP * HEAD_D * T_SEQ];     // rounded, [grp][dim][key]
__device__ float g_Y [T_SEQ * C_EMB];              // rounded
__device__ float2 g_rope[T_SEQ * (HEAD_D / 2)];    // (cos,sin)

// ---------------------------------------------------------------------------
// helpers
// ---------------------------------------------------------------------------
__device__ __forceinline__ unsigned f2tf(float x) {
    unsigned r;
    asm("cvt.rna.tf32.f32 %0, %1;" : "=r"(r) : "f"(x));
    return r;
}
__device__ __forceinline__ float ftf(float x) {
    return __uint_as_float(f2tf(x));
}

__device__ __forceinline__ void mma_tf32(float c[4], const unsigned a[4],
                                         unsigned b0, unsigned b1) {
    asm volatile(
        "mma.sync.aligned.m16n8k8.row.col.f32.tf32.tf32.f32 "
        "{%0,%1,%2,%3}, {%4,%5,%6,%7}, {%8,%9}, {%0,%1,%2,%3};\n"
        : "+f"(c[0]), "+f"(c[1]), "+f"(c[2]), "+f"(c[3])
        : "r"(a[0]), "r"(a[1]), "r"(a[2]), "r"(a[3]), "r"(b0), "r"(b1));
}

__device__ __forceinline__ void ldsm4(unsigned r[4], uint32_t addr) {
    asm volatile(
        "ldmatrix.sync.aligned.m8n8.x4.shared.b16 {%0,%1,%2,%3}, [%4];\n"
        : "=r"(r[0]), "=r"(r[1]), "=r"(r[2]), "=r"(r[3]) : "r"(addr));
}

__device__ __forceinline__ void cp16(uint32_t dst_smem, const void* src) {
    asm volatile("cp.async.cg.shared.global [%0], [%1], 16;\n"
                 :: "r"(dst_smem), "l"(src));
}
__device__ __forceinline__ void cp_commit() {
    asm volatile("cp.async.commit_group;\n");
}
template <int N>
__device__ __forceinline__ void cp_wait() {
    asm volatile("cp.async.wait_group %0;\n" :: "n"(N));
}

// ---------------------------------------------------------------------------
// prep: fused round(x) + rope table + both weight transposes.
// Block-range dispatch, 256 threads/block.
//   [0, 2048)          : round x (4 floats/thread)
//   [2048, 2304)       : rope table
//   [2304, 3840)       : transpose+round w_attn (48x32 tiles of 32x32)
//   [3840, 4864)       : transpose+round w_proj (32x32 tiles)
// ---------------------------------------------------------------------------
#define PREP_BLOCKS 4864

__global__ void prep(const float* __restrict__ x,
                     const float* __restrict__ wa,
                     const float* __restrict__ wp)
{
    __shared__ float tile[32][33];
    int b = blockIdx.x;
    int tid = threadIdx.x;

    if (b < 2048) {                     // round x
        int i = (b * 256 + tid) * 4;
        float4 v = *(const float4*)(x + i);
        v.x = ftf(v.x); v.y = ftf(v.y); v.z = ftf(v.z); v.w = ftf(v.w);
        *(float4*)(g_x + i) = v;
        return;
    }
    b -= 2048;
    if (b < 256) {                      // rope table (identical math)
        int idx = b * 256 + tid;
        int t = idx >> 5;
        int i = idx & 31;
        int d = 2 * i;
        float inv = powf(10000.0f, -(float)d / (float)HEAD_D);
        float ang = (float)t * inv;
        float s, c;
        sincosf(ang, &s, &c);
        g_rope[idx] = make_float2(c, s);
        return;
    }
    b -= 256;

    const float* in;
    float* out;
    int C, bx, by;
    if (b < 1536) { in = wa; out = g_waT; C = QKV_DIM; bx = b % 48; by = b / 48; }
    else { b -= 1536; in = wp; out = g_wpT; C = C_EMB; bx = b % 32; by = b / 32; }
    const int R = C_EMB;
    int c0 = bx * 32, r0 = by * 32;
    int tx = tid & 31, ty = tid >> 5;   // ty 0..7
    #pragma unroll
    for (int i = 0; i < 32; i += 8)
        tile[ty + i][tx] = in[(size_t)(r0 + ty + i) * C + c0 + tx];
    __syncthreads();
    #pragma unroll
    for (int i = 0; i < 32; i += 8)
        out[(size_t)(c0 + ty + i) * R + r0 + tx] = ftf(tile[tx][ty + i]);
}

// ---------------------------------------------------------------------------
// RoPE + split, Vt written directly.
// grid (T_SEQ/32, 24): block = 32 t-rows x one 64-col slot.
// slot 0..3 = Q heads (rope, x1/8), slot 4 = K (rope), slot 5 = V (no rope,
// in-smem 64x32 transpose -> Vt [grp][dim][key], coalesced along t).
// All rounding sites identical to previous version -> bit-identical outputs.
// ---------------------------------------------------------------------------
__global__ void rope_split(const float* __restrict__ qkv)
{
    __shared__ float vt[64][33];
    const int t0   = blockIdx.x * 32;
    const int s    = blockIdx.y;          // 0..23
    const int gq   = s / 6;
    const int slot = s % 6;
    const int base = gq * (6 * HEAD_D) + slot * HEAD_D;
    const int tid  = threadIdx.x;
    const int p    = tid & 31;            // pair index
    const int d    = 2 * p;

    if (slot < 4) {
        const int h = gq * 4 + slot;
        #pragma unroll
        for (int i = 0; i < 4; i++) {
            int t = t0 + (tid >> 5) + i * 8;
            float x0 = qkv[(size_t)t * QKV_DIM + base + d];
            float x1 = qkv[(size_t)t * QKV_DIM + base + d + 1];
            float2 cs = g_rope[t * 32 + p];
            float r0 = x0 * cs.x - x1 * cs.y;
            float r1 = x1 * cs.x + x0 * cs.y;
            float* dst = g_Q + ((size_t)h * T_SEQ + t) * HEAD_D + d;
            dst[0] = ftf(r0 * 0.125f);
            dst[1] = ftf(r1 * 0.125f);
        }
    } else if (slot == 4) {
        #pragma unroll
        for (int i = 0; i < 4; i++) {
            int t = t0 + (tid >> 5) + i * 8;
            float x0 = qkv[(size_t)t * QKV_DIM + base + d];
            float x1 = qkv[(size_t)t * QKV_DIM + base + d + 1];
            float2 cs = g_rope[t * 32 + p];
            float r0 = x0 * cs.x - x1 * cs.y;
            float r1 = x1 * cs.x + x0 * cs.y;
            float* dst = g_K + ((size_t)gq * T_SEQ + t) * HEAD_D + d;
            dst[0] = ftf(r0);
            dst[1] = ftf(r1);
        }
    } else {
        // V: no rope; transpose in smem, write Vt coalesced along t
        #pragma unroll
        for (int i = 0; i < 4; i++) {
            int tr = (tid >> 5) + i * 8;
            int t  = t0 + tr;
            float x0 = qkv[(size_t)t * QKV_DIM + base + d];
            float x1 = qkv[(size_t)t * QKV_DIM + base + d + 1];
            vt[d    ][tr] = ftf(x0);
            vt[d + 1][tr] = ftf(x1);
        }
        __syncthreads();
        float* dst = g_Vt + (size_t)gq * HEAD_D * T_SEQ;
        #pragma unroll
        for (int j = 0; j < 8; j++) {
            int e = tid + j * 256;
            int dd = e >> 5, tt = e & 31;
            dst[(size_t)dd * T_SEQ + t0 + tt] = vt[dd][tt];
        }
    }
}

// ---------------------------------------------------------------------------
// tf32 GEMM (R15 config — best measured): B transposed in gmem,
// block tile 64x128, 8 warps (2Mx4N), warp tile 32x32, 256 threads,
// K-step 32, 2-stage cp.async pipeline, LDSM fragment loads.
// ---------------------------------------------------------------------------
#define AS_STRIDE 36
#define BS_STRIDE 36
#define A_WORDS   (64 * AS_STRIDE)           // 2304
#define B_WORDS   (128 * BS_STRIDE)          // 4608
#define STAGE_WORDS (A_WORDS + B_WORDS)      // 6912
#define GEMM_SMEM (2 * STAGE_WORDS * 4)      // 55296 B

__device__ __forceinline__ void gemm_load_stage(
    uint32_t sbase, const float* A, const float* Bt,
    int m0, int n0, int k0, int K, int tid)
{
    uint32_t as = sbase;
    uint32_t bs = sbase + A_WORDS * 4;
    #pragma unroll
    for (int i = 0; i < 2; i++) {
        int f = tid + i * 256;
        int row = f >> 3, kc = (f & 7) * 4;
        cp16(as + (row * AS_STRIDE + kc) * 4,
             A + (size_t)(m0 + row) * K + k0 + kc);
    }
    #pragma unroll
    for (int i = 0; i < 4; i++) {
        int f = tid + i * 256;
        int row = f >> 3, kc = (f & 7) * 4;
        cp16(bs + (row * BS_STRIDE + kc) * 4,
             Bt + (size_t)(n0 + row) * K + k0 + kc);
    }
}

__global__ __launch_bounds__(256) void gemm_tf32(
    const float* __restrict__ A, const float* __restrict__ Bt,
    float* __restrict__ C, int M, int N, int K)
{
    extern __shared__ float sm[];
    const uint32_t smem_u32 = (uint32_t)__cvta_generic_to_shared(sm);

    const int tid  = threadIdx.x;
    const int wid  = tid >> 5;
    const int lane = tid & 31;
    const int g    = lane >> 2;
    const int t    = lane & 3;
    const int wm   = wid & 1;
    const int wn   = wid >> 1;
    const int m0   = blockIdx.y * 64;
    const int n0   = blockIdx.x * 128;

    const int lrow = (lane & 7) + ((lane >> 3) & 1) * 8;
    const int lcol = (lane >> 4) * 4;

    int a_off[2], b_off[2];
    #pragma unroll
    for (int mt = 0; mt < 2; mt++)
        a_off[mt] = (wm * 32 + mt * 16 + lrow) * AS_STRIDE + lcol;
    #pragma unroll
    for (int p = 0; p < 2; p++)
        b_off[p] = A_WORDS + (wn * 32 + p * 16 + lrow) * BS_STRIDE + lcol;

    float acc[2][4][4];
    #pragma unroll
    for (int mt = 0; mt < 2; mt++)
        #pragma unroll
        for (int nt = 0; nt < 4; nt++)
            #pragma unroll
            for (int i = 0; i < 4; i++) acc[mt][nt][i] = 0.0f;

    gemm_load_stage(smem_u32, A, Bt, m0, n0, 0, K, tid);
    cp_commit();

    int s = 0;
    for (int k0 = 0; k0 < K; k0 += 32) {
        cp_wait<0>();
        __syncthreads();
        if (k0 + 32 < K) {
            gemm_load_stage(smem_u32 + (s ^ 1) * STAGE_WORDS * 4,
                            A, Bt, m0, n0, k0 + 32, K, tid);
        }
        cp_commit();

        const uint32_t sb = smem_u32 + s * STAGE_WORDS * 4;
        #pragma unroll
        for (int kk = 0; kk < 4; kk++) {
            const int k8 = kk * 8;
            unsigned a[2][4], bf[2][4];
            ldsm4(a[0],  sb + (a_off[0] + k8) * 4);
            ldsm4(a[1],  sb + (a_off[1] + k8) * 4);
            ldsm4(bf[0], sb + (b_off[0] + k8) * 4);
            ldsm4(bf[1], sb + (b_off[1] + k8) * 4);
            #pragma unroll
            for (int p = 0; p < 2; p++)
                #pragma unroll
                for (int sub = 0; sub < 2; sub++) {
                    unsigned b0 = bf[p][sub], b1 = bf[p][2 + sub];
                    #pragma unroll
                    for (int mt = 0; mt < 2; mt++)
                        mma_tf32(acc[mt][2 * p + sub], a[mt], b0, b1);
                }
        }
        s ^= 1;
    }

    #pragma unroll
    for (int mt = 0; mt < 2; mt++) {
        int r0 = m0 + wm * 32 + mt * 16 + g;
        #pragma unroll
        for (int nt = 0; nt < 4; nt++) {
            int c0 = n0 + wn * 32 + nt * 8 + 2 * t;
            *(float2*)&C[(size_t)r0 * N + c0] =
                make_float2(acc[mt][nt][0], acc[mt][nt][1]);
            *(float2*)&C[(size_t)(r0 + 8) * N + c0] =
                make_float2(acc[mt][nt][2], acc[mt][nt][3]);
        }
    }
}

// ---------------------------------------------------------------------------
// Flash-style causal attention — R10/R15 configuration (best measured).
// 128 threads (4 warps), 64 queries/CTA, smem P, 2-buffer cp.async, LPT,
// LDSM fragment loads (K [key][dim], Vt [dim][key], P [q][key]).
// ---------------------------------------------------------------------------
#define KS_STRIDE 68
#define VS_STRIDE 68
#define PS_STRIDE 68
#define K_WORDS (64 * KS_STRIDE)
#define V_WORDS (64 * VS_STRIDE)
#define P_WORDS (64 * PS_STRIDE)
#define ATTN_SMEM ((2 * K_WORDS + 2 * V_WORDS + P_WORDS) * 4)   // 87040 B

__device__ __forceinline__ void attn_load_tile(
    uint32_t kbuf, uint32_t vbuf,
    const float* Kg, const float* VgT, int kbase, int tid)
{
    #pragma unroll
    for (int i = 0; i < 8; i++) {
        int f = tid + i * 128;
        int row = f >> 4;
        int c = (f & 15) * 4;
        cp16(kbuf + (row * KS_STRIDE + c) * 4,
             Kg + (size_t)(kbase + row) * HEAD_D + c);
        cp16(vbuf + (row * VS_STRIDE + c) * 4,
             VgT + (size_t)row * T_SEQ + kbase + c);
    }
}

__global__ __launch_bounds__(128) void attn_kernel()
{
    extern __shared__ float sm[];
    float* Ps = sm + 2 * K_WORDS + 2 * V_WORDS;
    const uint32_t su = (uint32_t)__cvta_generic_to_shared(sm);
    const uint32_t kbu[2] = { su, su + K_WORDS * 4 };
    const uint32_t vbu[2] = { su + 2 * K_WORDS * 4, su + (2 * K_WORDS + V_WORDS) * 4 };
    const uint32_t psu    = su + (2 * K_WORDS + 2 * V_WORDS) * 4;

    const int h    = blockIdx.x;
    const int qt   = gridDim.y - 1 - blockIdx.y;   // LPT
    const int tid  = threadIdx.x;
    const int w    = tid >> 5;
    const int lane = tid & 31;
    const int g    = lane >> 2;
    const int t    = lane & 3;
    const int grp  = h >> 2;
    const int qw0  = qt * 64 + w * 16;

    const int lrow = (lane & 7) + ((lane >> 3) & 1) * 8;
    const int lcol = (lane >> 4) * 4;

    const float* Kg  = g_K  + (size_t)grp * T_SEQ * HEAD_D;
    const float* VgT = g_Vt + (size_t)grp * HEAD_D * T_SEQ;

    unsigned qa[8][4];
    {
        const float* Qb = g_Q + ((size_t)h * T_SEQ + qw0) * HEAD_D;
        #pragma unroll
        for (int ks = 0; ks < 8; ks++) {
            qa[ks][0] = __float_as_uint(Qb[(size_t)(g    ) * HEAD_D + ks * 8 + t    ]);
            qa[ks][1] = __float_as_uint(Qb[(size_t)(g + 8) * HEAD_D + ks * 8 + t    ]);
            qa[ks][2] = __float_as_uint(Qb[(size_t)(g    ) * HEAD_D + ks * 8 + t + 4]);
            qa[ks][3] = __float_as_uint(Qb[(size_t)(g + 8) * HEAD_D + ks * 8 + t + 4]);
        }
    }

    float oc[8][4];
    #pragma unroll
    for (int nt = 0; nt < 8; nt++)
        #pragma unroll
        for (int i = 0; i < 4; i++) oc[nt][i] = 0.0f;
    float l0 = 0.0f, l1 = 0.0f;

    attn_load_tile(kbu[0], vbu[0], Kg, VgT, 0, tid);
    cp_commit();

    int buf = 0;
    for (int kt = 0; kt <= qt; kt++) {
        const int kbase = kt * 64;
        cp_wait<0>();
        __syncthreads();
        if (kt < qt) {
            attn_load_tile(kbu[buf ^ 1], vbu[buf ^ 1], Kg, VgT, kbase + 64, tid);
        }
        cp_commit();

        const uint32_t kb = kbu[buf];
        const uint32_t vb = vbu[buf];

        // S = Q @ K^T
        float sc[8][4];
        #pragma unroll
        for (int nt = 0; nt < 8; nt++)
            #pragma unroll
            for (int i = 0; i < 4; i++) sc[nt][i] = 0.0f;

        #pragma unroll
        for (int ks = 0; ks < 8; ks++) {
            #pragma unroll
            for (int p = 0; p < 4; p++) {
                unsigned bf[4];
                ldsm4(bf, kb + ((p * 16 + lrow) * KS_STRIDE + ks * 8 + lcol) * 4);
                mma_tf32(sc[2 * p    ], qa[ks], bf[0], bf[2]);
                mma_tf32(sc[2 * p + 1], qa[ks], bf[1], bf[3]);
            }
        }

        // exp (+causal mask on diagonal), accumulate l, store P (tf32)
        const bool diag = (kt == qt);
        #pragma unroll
        for (int nt = 0; nt < 8; nt++) {
            int k0 = kbase + nt * 8 + 2 * t;
            float p0 = __expf(sc[nt][0]);
            float p1 = __expf(sc[nt][1]);
            float p2 = __expf(sc[nt][2]);
            float p3 = __expf(sc[nt][3]);
            if (diag) {
                int q0 = qw0 + g, q1 = qw0 + g + 8;
                if (k0     > q0) p0 = 0.0f;
                if (k0 + 1 > q0) p1 = 0.0f;
                if (k0     > q1) p2 = 0.0f;
                if (k0 + 1 > q1) p3 = 0.0f;
            }
            l0 += p0 + p1;
            l1 += p2 + p3;
            int c = nt * 8 + 2 * t;
            Ps[(w * 16 + g    ) * PS_STRIDE + c    ] = ftf(p0);
            Ps[(w * 16 + g    ) * PS_STRIDE + c + 1] = ftf(p1);
            Ps[(w * 16 + g + 8) * PS_STRIDE + c    ] = ftf(p2);
            Ps[(w * 16 + g + 8) * PS_STRIDE + c + 1] = ftf(p3);
        }
        __syncwarp();   // Ps slab is warp-private

        // O += P @ V
        #pragma unroll
        for (int ks = 0; ks < 8; ks++) {
            unsigned pa[4];
            ldsm4(pa, psu + ((w * 16 + lrow) * PS_STRIDE + ks * 8 + lcol) * 4);
            #pragma unroll
            for (int p = 0; p < 4; p++) {
                unsigned bf[4];
                ldsm4(bf, vb + ((p * 16 + lrow) * VS_STRIDE + ks * 8 + lcol) * 4);
                mma_tf32(oc[2 * p    ], pa, bf[0], bf[2]);
                mma_tf32(oc[2 * p + 1], pa, bf[1], bf[3]);
            }
        }
        buf ^= 1;
    }

    l0 += __shfl_xor_sync(0xffffffff, l0, 1);
    l0 += __shfl_xor_sync(0xffffffff, l0, 2);
    l1 += __shfl_xor_sync(0xffffffff, l1, 1);
    l1 += __shfl_xor_sync(0xffffffff, l1, 2);
    float inv0 = 1.0f / l0;
    float inv1 = 1.0f / l1;

    float* Y0 = g_Y + (size_t)(qw0 + g    ) * C_EMB + h * HEAD_D;
    float* Y1 = g_Y + (size_t)(qw0 + g + 8) * C_EMB + h * HEAD_D;
    #pragma unroll
    for (int nt = 0; nt < 8; nt++) {
        int c = nt * 8 + 2 * t;
        *(float2*)(Y0 + c) = make_float2(ftf(oc[nt][0] * inv0), ftf(oc[nt][1] * inv0));
        *(float2*)(Y1 + c) = make_float2(ftf(oc[nt][2] * inv1), ftf(oc[nt][3] * inv1));
    }
}

// ---------------------------------------------------------------------------
extern "C" void kernel_launch(void* const* d_in, const int* in_sizes, int n_in,
                              void* d_out, int out_size)
{
    const float* x      = (const float*)d_in[0];   // [1,2048,1024]
    const float* w_attn = (const float*)d_in[1];   // [1024,1536]
    const float* w_proj = (const float*)d_in[2];   // [1024,1024]
    float* out = (float*)d_out;                    // [1,2048,1024]

    float *xr, *qkv, *Y, *waT, *wpT;
    cudaGetSymbolAddress((void**)&xr,  g_x);
    cudaGetSymbolAddress((void**)&waT, g_waT);
    cudaGetSymbolAddress((void**)&wpT, g_wpT);
    cudaGetSymbolAddress((void**)&qkv, g_qkv);
    cudaGetSymbolAddress((void**)&Y,   g_Y);

    cudaFuncSetAttribute(gemm_tf32,
                         cudaFuncAttributeMaxDynamicSharedMemorySize, GEMM_SMEM);
    cudaFuncSetAttribute(attn_kernel,
                         cudaFuncAttributeMaxDynamicSharedMemorySize, ATTN_SMEM);

    // launch 0: fused prep (round x + rope table + weight transposes)
    prep<<<PREP_BLOCKS, 256>>>(x, w_attn, w_proj);
    // launch 1: QKV = x @ w_attn
    {
        dim3 grid(QKV_DIM / 128, T_SEQ / 64);
        gemm_tf32<<<grid, 256, GEMM_SMEM>>>(xr, waT, qkv, T_SEQ, QKV_DIM, C_EMB);
    }
    // launch 2: RoPE + split (writes Q, K, Vt directly)
    {
        dim3 grid(T_SEQ / 32, 24);
        rope_split<<<grid, 256>>>(qkv);
    }
    // launch 3 (PROFILED): attention
    {
        dim3 grid(N_HEAD, T_SEQ / 64);
        attn_kernel<<<grid, 128, ATTN_SMEM>>>();
    }
    // launch 4: out = Y @ w_proj
    {
        dim3 grid(C_EMB / 128, T_SEQ / 64);
        gemm_tf32<<<grid, 256, GEMM_SMEM>>>(Y, wpT, out, T_SEQ, C_EMB, C_EMB);
    }
}